// round 14
// baseline (speedup 1.0000x reference)
#include <cuda_runtime.h>
#include <cuda_fp16.h>
#include <cstdint>
#include <math.h>

// Problem constants
#define P_NUM 64
#define B_NUM 32
#define D_DIM 512
#define H_DIM 2048
#define E_NUM 16
#define N_TOK (P_NUM * B_NUM)        // 2048 tokens
#define N_ROWS (N_TOK * 2)           // 4096 assignment rows

// ---- device scratch. NEVER passed as kernel args from host (host-shadow/ATS
// trap confirmed R10). All kernels reference these symbols in device code. ----
__device__ int   g_cnt[E_NUM];
__device__ int   g_tok [E_NUM][N_TOK];
__device__ int   g_row [E_NUM][N_TOK];
__device__ float g_gate[E_NUM][N_TOK];

// pre-split f16 operands (u32 = packed pair of f16 along k)
__device__ __align__(16) uint32_t g_xs_hi[(size_t)N_TOK * (D_DIM / 2)];
__device__ __align__(16) uint32_t g_xs_lo[(size_t)N_TOK * (D_DIM / 2)];
__device__ __align__(16) uint32_t g_Hs_hi[(size_t)N_ROWS * (H_DIM / 2)];
__device__ __align__(16) uint32_t g_Hs_lo[(size_t)N_ROWS * (H_DIM / 2)];
// W transposed, slab-major: [E][K/32][N][16] u32
__device__ __align__(16) uint32_t g_w1t_hi[(size_t)E_NUM * (D_DIM / 32) * H_DIM * 16];
__device__ __align__(16) uint32_t g_w1t_lo[(size_t)E_NUM * (D_DIM / 32) * H_DIM * 16];
__device__ __align__(16) uint32_t g_w2t_hi[(size_t)E_NUM * (H_DIM / 32) * D_DIM * 16];
__device__ __align__(16) uint32_t g_w2t_lo[(size_t)E_NUM * (H_DIM / 32) * D_DIM * 16];

__device__ float g_Y [(size_t)N_ROWS * D_DIM]; // split-0 output
__device__ float g_Y2[(size_t)N_ROWS * D_DIM]; // split-1 output

// ===========================================================================
// helpers
// ===========================================================================
__device__ __forceinline__ void mma_f16(float* c,
                                        uint32_t a0, uint32_t a1, uint32_t a2, uint32_t a3,
                                        uint32_t b0, uint32_t b1) {
    asm volatile(
        "mma.sync.aligned.m16n8k16.row.col.f32.f16.f16.f32 "
        "{%0,%1,%2,%3}, {%4,%5,%6,%7}, {%8,%9}, {%0,%1,%2,%3};"
        : "+f"(c[0]), "+f"(c[1]), "+f"(c[2]), "+f"(c[3])
        : "r"(a0), "r"(a1), "r"(a2), "r"(a3), "r"(b0), "r"(b1));
}

__device__ __forceinline__ void ldm_x4(uint32_t& r0, uint32_t& r1,
                                       uint32_t& r2, uint32_t& r3, uint32_t addr) {
    asm volatile(
        "ldmatrix.sync.aligned.m8n8.x4.shared.b16 {%0,%1,%2,%3}, [%4];"
        : "=r"(r0), "=r"(r1), "=r"(r2), "=r"(r3) : "r"(addr));
}

__device__ __forceinline__ uint32_t smem_addr(const void* p) {
    return (uint32_t)__cvta_generic_to_shared(p);
}

__device__ __forceinline__ void cp_async16(uint32_t dst, const void* src, int src_bytes) {
    asm volatile("cp.async.cg.shared.global [%0], [%1], 16, %2;"
                 :: "r"(dst), "l"(src), "r"(src_bytes) : "memory");
}
__device__ __forceinline__ void cp_commit() {
    asm volatile("cp.async.commit_group;" ::: "memory");
}

__device__ __forceinline__ uint32_t pack2h(__half e0, __half e1) {
    return (uint32_t)__half_as_ushort(e0) |
           ((uint32_t)__half_as_ushort(e1) << 16);
}

__device__ __forceinline__ void split_pack(float v0, float v1,
                                           uint32_t& hi, uint32_t& lo) {
    __half h0 = __float2half_rn(v0);
    __half h1 = __float2half_rn(v1);
    __half l0 = __float2half_rn(v0 - __half2float(h0));
    __half l1 = __float2half_rn(v1 - __half2float(h1));
    hi = pack2h(h0, h1);
    lo = pack2h(l0, l1);
}

// ===========================================================================
// small kernels
// ===========================================================================
__global__ void reset_kernel() {
    if (threadIdx.x < E_NUM) g_cnt[threadIdx.x] = 0;
}

__global__ void gating_kernel(const float* __restrict__ x,
                              const float* __restrict__ wg) {
    int t = blockIdx.x;
    __shared__ float xs[D_DIM];
    __shared__ float vals[E_NUM];
    int tid = threadIdx.x; // 32

    const float4* xr = reinterpret_cast<const float4*>(x + (size_t)t * D_DIM);
    float4* xs4 = reinterpret_cast<float4*>(xs);
    #pragma unroll
    for (int i = tid; i < D_DIM / 4; i += 32) xs4[i] = xr[i];
    __syncwarp();

    if (tid < E_NUM) {
        float acc = 0.f;
        #pragma unroll 8
        for (int d = 0; d < D_DIM; d++) acc += xs[d] * wg[d * E_NUM + tid];
        vals[tid] = acc;
    }
    __syncwarp();

    if (tid == 0) {
        float v1 = -INFINITY, v2 = -INFINITY;
        int i1 = 0, i2 = 0;
        #pragma unroll
        for (int e = 0; e < E_NUM; e++) {
            float v = vals[e];
            if (v > v1) { v2 = v1; i2 = i1; v1 = v; i1 = e; }
            else if (v > v2) { v2 = v; i2 = e; }
        }
        float ex = __expf(v2 - v1);
        float inv = 1.f / (1.f + ex);
        int p1 = atomicAdd(&g_cnt[i1], 1);
        g_tok[i1][p1] = t; g_row[i1][p1] = 2 * t;     g_gate[i1][p1] = inv;
        int p2 = atomicAdd(&g_cnt[i2], 1);
        g_tok[i2][p2] = t; g_row[i2][p2] = 2 * t + 1; g_gate[i2][p2] = ex * inv;
    }
}

// ===========================================================================
// conversion kernels: fp32 -> f16 hi/lo packed pairs
// ===========================================================================
__global__ void convert_x(const float* __restrict__ x) {
    int t = blockIdx.x;
    int c = threadIdx.x;          // 0..255
    float2 v = *reinterpret_cast<const float2*>(x + (size_t)t * D_DIM + 2 * c);
    uint32_t hi, lo;
    split_pack(v.x, v.y, hi, lo);
    g_xs_hi[(size_t)t * (D_DIM / 2) + c] = hi;
    g_xs_lo[(size_t)t * (D_DIM / 2) + c] = lo;
}

// W [E][K][N] fp32 -> Wt [E][K/32][N][16] u32 (packed f16 pairs along k)
template<int K, int N, bool W1>
__global__ __launch_bounds__(256)
void convert_w(const float* __restrict__ w) {
    __shared__ float tile[32][65];
    const int e  = blockIdx.z;
    const int sl = blockIdx.y;
    const int nt = blockIdx.x;    // 64-wide n tile
    const int tid = threadIdx.x;

    const float* src = w + ((size_t)e * K + sl * 32) * N + nt * 64;
    const int kk = tid >> 3;            // 0..31
    const int nn = (tid & 7) * 8;       // 0..56
    float4 v0 = *reinterpret_cast<const float4*>(src + (size_t)kk * N + nn);
    float4 v1 = *reinterpret_cast<const float4*>(src + (size_t)kk * N + nn + 4);
    tile[kk][nn + 0] = v0.x; tile[kk][nn + 1] = v0.y;
    tile[kk][nn + 2] = v0.z; tile[kk][nn + 3] = v0.w;
    tile[kk][nn + 4] = v1.x; tile[kk][nn + 5] = v1.y;
    tile[kk][nn + 6] = v1.z; tile[kk][nn + 7] = v1.w;
    __syncthreads();

    uint32_t* oh = W1 ? g_w1t_hi : g_w2t_hi;
    uint32_t* ol = W1 ? g_w1t_lo : g_w2t_lo;
    const size_t obase = (((size_t)e * (K / 32) + sl) * N + (size_t)nt * 64) * 16;
    const int c = tid & 15;
    #pragma unroll
    for (int b = 0; b < 4; b++) {
        int n = (tid >> 4) + b * 16;   // 0..63
        uint32_t hi, lo;
        split_pack(tile[2 * c][n], tile[2 * c + 1][n], hi, lo);
        oh[obase + (size_t)n * 16 + c] = hi;
        ol[obase + (size_t)n * 16 + c] = lo;
    }
}

// ===========================================================================
// Grouped GEMM via mma.sync f16 (3x split): CTA tile 128x256, 512 threads,
// 16 warps of 64x32 tiles (16 acc chains each -> 256 chains/SM), cp.async
// double-buffered staging, ldmatrix fragments. K-slab 32.
// Stage layout (bytes): [Ah 128*80 | Al 128*80 | Bh 256*80 | Bl 256*80] = 61440
// ===========================================================================
#define STG_BYTES 61440
#define A_SUB 10240
#define B_OFF 20480
#define B_SUB 20480
#define DSM_TOTAL (2 * STG_BYTES)

template<int KDIM, int NTOT, bool RELU, int NSPLIT>
__global__ __launch_bounds__(512, 1)
void moe_mma(const float* __restrict__ bias) {
    const int e     = blockIdx.z / NSPLIT;
    const int split = blockIdx.z % NSPLIT;
    const int cnt = g_cnt[e];
    const int m0  = blockIdx.y * 128;
    if (m0 >= cnt) return;
    const int n0  = blockIdx.x * 256;

    const int KSEG  = KDIM / NSPLIT;
    const int kb    = split * KSEG;
    const int NSLAB = KDIM / 32;
    const int slab0 = kb / 32;
    const int NS    = KSEG / 32;

    extern __shared__ __align__(16) uint32_t dsm[];
    __shared__ float bias_s[256];

    const int tid = threadIdx.x;
    const int wid = tid >> 5, lid = tid & 31;
    const int wm = wid & 1;        // 2 M blocks of 64
    const int wn = wid >> 1;       // 8 N blocks of 32
    const int qid = lid >> 2;
    const int tig = lid & 3;

    const uint32_t smem_base = smem_addr(dsm);

    // device-symbol operand plumbing
    const uint32_t* Ahg = RELU ? g_xs_hi : g_Hs_hi;
    const uint32_t* Alg = RELU ? g_xs_lo : g_Hs_lo;
    const uint32_t* Whg = RELU ? g_w1t_hi : g_w2t_hi;
    const uint32_t* Wlg = RELU ? g_w1t_lo : g_w2t_lo;
    float* DstF = (split == 0) ? g_Y : g_Y2;

    if (tid < 256) bias_s[tid] = bias[(size_t)e * NTOT + n0 + tid];

    // ---- staging mappings ----
    // A: threads 0..255 -> row-eq (h = t>>7, r = t&127), 4 x cp.async16 (64 B)
    const int ha = tid >> 7;             // valid for tid<256: 0=hi,1=lo
    const int ra = tid & 127;
    const int mrow = m0 + ra;
    const bool mvalid = (mrow < cnt) && (tid < 256);
    const int apred = (mrow < cnt) ? 16 : 0;
    const int aidx = (mrow < cnt) ? (RELU ? g_tok[e][mrow] : g_row[e][mrow]) : 0;
    const uint32_t* agp = (ha ? Alg : Ahg) + (size_t)aidx * (KDIM / 2) + (kb >> 1);
    const uint32_t dstA = smem_base + (uint32_t)(ha * A_SUB + ra * 80);
    // B: all 512 threads -> row-eq (h = t>>8, r = t&255), 4 x cp.async16
    const int hb = tid >> 8;
    const int rb = tid & 255;
    const uint32_t* wgp = (hb ? Wlg : Whg)
        + ((size_t)e * NSLAB + slab0) * NTOT * 16 + (size_t)(n0 + rb) * 16;
    const uint32_t dstB = smem_base + (uint32_t)(B_OFF + hb * B_SUB + rb * 80);

    // ---- ldmatrix base addresses (byte, stage 0) ----
    const uint32_t aAh = smem_base + (uint32_t)((wm * 64 + (lid & 15)) * 80 + (lid >> 4) * 16);
    const uint32_t aAl = aAh + A_SUB;
    const int brow = wn * 32 + (lid >> 4) * 8 + (lid & 7);
    const int bcol = ((lid >> 3) & 1) * 16;   // bytes
    const uint32_t aBh = smem_base + (uint32_t)(B_OFF + brow * 80 + bcol);
    const uint32_t aBl = aBh + B_SUB;

    float acc[4][4][4];
    #pragma unroll
    for (int i = 0; i < 4; i++)
        #pragma unroll
        for (int j = 0; j < 4; j++)
            #pragma unroll
            for (int p = 0; p < 4; p++) acc[i][j][p] = 0.f;

    // ---- issue copies for slab 0 into stage 0 ----
    if (tid < 256) {
        #pragma unroll
        for (int j = 0; j < 4; j++) cp_async16(dstA + j * 16, agp + j * 4, apred);
    }
    #pragma unroll
    for (int j = 0; j < 4; j++) cp_async16(dstB + j * 16, wgp + j * 4, 16);
    cp_commit();

    for (int s = 0; s < NS; s++) {
        const uint32_t stg = (uint32_t)(s & 1) * STG_BYTES;

        // issue copies for slab s+1 into the other stage
        if (s + 1 < NS) {
            const uint32_t nst = (uint32_t)((s + 1) & 1) * STG_BYTES;
            if (tid < 256) {
                const uint32_t* ap = agp + (size_t)(s + 1) * 16;
                #pragma unroll
                for (int j = 0; j < 4; j++)
                    cp_async16(dstA + nst + j * 16, ap + j * 4, apred);
            }
            const uint32_t* bp = wgp + (size_t)(s + 1) * NTOT * 16;
            #pragma unroll
            for (int j = 0; j < 4; j++)
                cp_async16(dstB + nst + j * 16, bp + j * 4, 16);
            cp_commit();
            asm volatile("cp.async.wait_group 1;" ::: "memory");
        } else {
            asm volatile("cp.async.wait_group 0;" ::: "memory");
        }
        __syncthreads();   // stage s fully visible to all warps

        #pragma unroll
        for (int ks = 0; ks < 2; ks++) {
            const uint32_t cb = stg + ks * 32;   // stage + 8-u32 column shift
            uint32_t bh[4][2], bl[4][2];
            #pragma unroll
            for (int jj = 0; jj < 2; jj++) {
                ldm_x4(bh[jj * 2][0], bh[jj * 2][1],
                       bh[jj * 2 + 1][0], bh[jj * 2 + 1][1],
                       aBh + jj * (16 * 80) + cb);
                ldm_x4(bl[jj * 2][0], bl[jj * 2][1],
                       bl[jj * 2 + 1][0], bl[jj * 2 + 1][1],
                       aBl + jj * (16 * 80) + cb);
            }
            #pragma unroll
            for (int i = 0; i < 4; i++) {
                uint32_t ah0, ah1, ah2, ah3, al0, al1, al2, al3;
                ldm_x4(ah0, ah1, ah2, ah3, aAh + i * (16 * 80) + cb);
                ldm_x4(al0, al1, al2, al3, aAl + i * (16 * 80) + cb);
                #pragma unroll
                for (int j = 0; j < 4; j++) {
                    mma_f16(acc[i][j], ah0, ah1, ah2, ah3, bh[j][0], bh[j][1]);
                    mma_f16(acc[i][j], al0, al1, al2, al3, bh[j][0], bh[j][1]);
                    mma_f16(acc[i][j], ah0, ah1, ah2, ah3, bl[j][0], bl[j][1]);
                }
            }
        }
        __syncthreads();   // all warps done with stage s before it is refilled
    }

    // ---- epilogue ----
    const bool add_bias = RELU || (split == 0);
    #pragma unroll
    for (int i = 0; i < 4; i++) {
        const int mr0 = m0 + wm * 64 + i * 16 + qid;
        const int mr1 = mr0 + 8;
        const bool v0 = (mr0 < cnt), v1 = (mr1 < cnt);
        const int dr0 = v0 ? g_row[e][mr0] : 0;
        const int dr1 = v1 ? g_row[e][mr1] : 0;
        const float gt0 = RELU ? 1.f : (v0 ? g_gate[e][mr0] : 0.f);
        const float gt1 = RELU ? 1.f : (v1 ? g_gate[e][mr1] : 0.f);
        #pragma unroll
        for (int j = 0; j < 4; j++) {
            const int cl = wn * 32 + j * 8 + tig * 2;
            const float bz0 = add_bias ? bias_s[cl]     : 0.f;
            const float bz1 = add_bias ? bias_s[cl + 1] : 0.f;
            if (RELU) {
                const size_t hcol = (size_t)((n0 + cl) >> 1);
                if (v0) {
                    float y0 = fmaxf(acc[i][j][0] + bz0, 0.f);
                    float y1 = fmaxf(acc[i][j][1] + bz1, 0.f);
                    uint32_t hi, lo;
                    split_pack(y0, y1, hi, lo);
                    g_Hs_hi[(size_t)dr0 * (NTOT / 2) + hcol] = hi;
                    g_Hs_lo[(size_t)dr0 * (NTOT / 2) + hcol] = lo;
                }
                if (v1) {
                    float y0 = fmaxf(acc[i][j][2] + bz0, 0.f);
                    float y1 = fmaxf(acc[i][j][3] + bz1, 0.f);
                    uint32_t hi, lo;
                    split_pack(y0, y1, hi, lo);
                    g_Hs_hi[(size_t)dr1 * (NTOT / 2) + hcol] = hi;
                    g_Hs_lo[(size_t)dr1 * (NTOT / 2) + hcol] = lo;
                }
            } else {
                if (v0) {
                    float2 o;
                    o.x = gt0 * (acc[i][j][0] + bz0);
                    o.y = gt0 * (acc[i][j][1] + bz1);
                    *reinterpret_cast<float2*>(DstF + (size_t)dr0 * NTOT + n0 + cl) = o;
                }
                if (v1) {
                    float2 o;
                    o.x = gt1 * (acc[i][j][2] + bz0);
                    o.y = gt1 * (acc[i][j][3] + bz1);
                    *reinterpret_cast<float2*>(DstF + (size_t)dr1 * NTOT + n0 + cl) = o;
                }
            }
        }
    }
}

// ===========================================================================
// out[t][d] = Y0[2t]+Y0[2t+1]+Y1[2t]+Y1[2t+1]
__global__ void combine_kernel(float* __restrict__ out) {
    int i = blockIdx.x * blockDim.x + threadIdx.x;
    if (i >= N_TOK * D_DIM / 4) return;
    int t  = i / (D_DIM / 4);
    int d4 = i % (D_DIM / 4);
    const float4* a0 = reinterpret_cast<const float4*>(g_Y  + (size_t)(2 * t)     * D_DIM) + d4;
    const float4* a1 = reinterpret_cast<const float4*>(g_Y  + (size_t)(2 * t + 1) * D_DIM) + d4;
    const float4* b0 = reinterpret_cast<const float4*>(g_Y2 + (size_t)(2 * t)     * D_DIM) + d4;
    const float4* b1 = reinterpret_cast<const float4*>(g_Y2 + (size_t)(2 * t + 1) * D_DIM) + d4;
    float4 p = *a0, q = *a1, r = *b0, s = *b1;
    reinterpret_cast<float4*>(out)[i] =
        make_float4(p.x + q.x + r.x + s.x, p.y + q.y + r.y + s.y,
                    p.z + q.z + r.z + s.z, p.w + q.w + r.w + s.w);
}

__global__ void aux_kernel(float* __restrict__ out, int out_size) {
    __shared__ float imp[E_NUM];
    int w = threadIdx.x >> 5, lane = threadIdx.x & 31;
    int cnt = g_cnt[w];
    float s = 0.f;
    for (int i = lane; i < cnt; i += 32) s += g_gate[w][i];
    #pragma unroll
    for (int off = 16; off > 0; off >>= 1) s += __shfl_down_sync(0xffffffffu, s, off);
    if (lane == 0) imp[w] = s;
    __syncthreads();
    if (threadIdx.x == 0) {
        float mean = 0.f;
        #pragma unroll
        for (int e = 0; e < E_NUM; e++) mean += imp[e];
        mean *= (1.f / E_NUM);
        float var = 0.f;
        #pragma unroll
        for (int e = 0; e < E_NUM; e++) { float d = imp[e] - mean; var += d * d; }
        var *= (1.f / (E_NUM - 1));
        float aux = 0.01f * var / (mean * mean + 1e-10f);
        if (out_size > N_TOK * D_DIM) out[out_size - 1] = aux;
    }
}

// ===========================================================================
extern "C" void kernel_launch(void* const* d_in, const int* in_sizes, int n_in,
                              void* d_out, int out_size) {
    const float* x  = (const float*)d_in[0];
    const float* wg = (const float*)d_in[1];
    const float* w1 = (const float*)d_in[2];
    const float* b1 = (const float*)d_in[3];
    const float* w2 = (const float*)d_in[4];
    const float* b2 = (const float*)d_in[5];
    float* out = (float*)d_out;

    cudaFuncSetAttribute(moe_mma<D_DIM, H_DIM, true, 1>,
                         cudaFuncAttributeMaxDynamicSharedMemorySize, DSM_TOTAL);
    cudaFuncSetAttribute(moe_mma<H_DIM, D_DIM, false, 2>,
                         cudaFuncAttributeMaxDynamicSharedMemorySize, DSM_TOTAL);

    reset_kernel<<<1, 32>>>();
    gating_kernel<<<N_TOK, 32>>>(x, wg);
    // pre-split operands to f16 hi/lo
    convert_x<<<N_TOK, 256>>>(x);
    convert_w<D_DIM, H_DIM, true ><<<dim3(H_DIM / 64, D_DIM / 32, E_NUM), 256>>>(w1);
    convert_w<H_DIM, D_DIM, false><<<dim3(D_DIM / 64, H_DIM / 32, E_NUM), 256>>>(w2);
    // GEMM1: g_Hs = relu(Xg @ W1 + b1); grid (2048/256=8, 16, 16)
    moe_mma<D_DIM, H_DIM, true, 1>
        <<<dim3(H_DIM / 256, N_TOK / 128, E_NUM), 512, DSM_TOTAL>>>(b1);
    // GEMM2 split-K=2: g_Y/g_Y2 = gate*(Hg @ W2 [+ b2 on split0]); grid (2, 16, 32)
    moe_mma<H_DIM, D_DIM, false, 2>
        <<<dim3(D_DIM / 256, N_TOK / 128, E_NUM * 2), 512, DSM_TOTAL>>>(b2);
    combine_kernel<<<(N_TOK * D_DIM / 4 + 255) / 256, 256>>>(out);
    aux_kernel<<<1, 512>>>(out, out_size);
}

// round 15
// speedup vs baseline: 1.1087x; 1.1087x over previous
#include <cuda_runtime.h>
#include <cuda_fp16.h>
#include <cstdint>
#include <math.h>

// Problem constants
#define P_NUM 64
#define B_NUM 32
#define D_DIM 512
#define H_DIM 2048
#define E_NUM 16
#define N_TOK (P_NUM * B_NUM)        // 2048 tokens
#define N_ROWS (N_TOK * 2)           // 4096 assignment rows

// ---- device scratch. NEVER passed as kernel args from host (host-shadow/ATS
// trap confirmed R10). All kernels reference these symbols in device code. ----
__device__ int   g_cnt[E_NUM];
__device__ int   g_tok [E_NUM][N_TOK];
__device__ int   g_row [E_NUM][N_TOK];
__device__ float g_gate[E_NUM][N_TOK];

// pre-split f16 operands (u32 = packed pair of f16 along k)
__device__ __align__(16) uint32_t g_xs_hi[(size_t)N_TOK * (D_DIM / 2)];
__device__ __align__(16) uint32_t g_xs_lo[(size_t)N_TOK * (D_DIM / 2)];
__device__ __align__(16) uint32_t g_Hs_hi[(size_t)N_ROWS * (H_DIM / 2)];
__device__ __align__(16) uint32_t g_Hs_lo[(size_t)N_ROWS * (H_DIM / 2)];
// W transposed, slab-major: [E][K/32][N][16] u32
__device__ __align__(16) uint32_t g_w1t_hi[(size_t)E_NUM * (D_DIM / 32) * H_DIM * 16];
__device__ __align__(16) uint32_t g_w1t_lo[(size_t)E_NUM * (D_DIM / 32) * H_DIM * 16];
__device__ __align__(16) uint32_t g_w2t_hi[(size_t)E_NUM * (H_DIM / 32) * D_DIM * 16];
__device__ __align__(16) uint32_t g_w2t_lo[(size_t)E_NUM * (H_DIM / 32) * D_DIM * 16];

__device__ float g_Y [(size_t)N_ROWS * D_DIM]; // split-0 output
__device__ float g_Y2[(size_t)N_ROWS * D_DIM]; // split-1 output
__device__ float g_Y3[(size_t)N_ROWS * D_DIM]; // split-2 output
__device__ float g_Y4[(size_t)N_ROWS * D_DIM]; // split-3 output

// ===========================================================================
// helpers
// ===========================================================================
__device__ __forceinline__ void mma_f16(float* c,
                                        uint32_t a0, uint32_t a1, uint32_t a2, uint32_t a3,
                                        uint32_t b0, uint32_t b1) {
    asm volatile(
        "mma.sync.aligned.m16n8k16.row.col.f32.f16.f16.f32 "
        "{%0,%1,%2,%3}, {%4,%5,%6,%7}, {%8,%9}, {%0,%1,%2,%3};"
        : "+f"(c[0]), "+f"(c[1]), "+f"(c[2]), "+f"(c[3])
        : "r"(a0), "r"(a1), "r"(a2), "r"(a3), "r"(b0), "r"(b1));
}

__device__ __forceinline__ void ldm_x4(uint32_t& r0, uint32_t& r1,
                                       uint32_t& r2, uint32_t& r3, uint32_t addr) {
    asm volatile(
        "ldmatrix.sync.aligned.m8n8.x4.shared.b16 {%0,%1,%2,%3}, [%4];"
        : "=r"(r0), "=r"(r1), "=r"(r2), "=r"(r3) : "r"(addr));
}

__device__ __forceinline__ uint32_t smem_addr(const void* p) {
    return (uint32_t)__cvta_generic_to_shared(p);
}

__device__ __forceinline__ void cp_async16(uint32_t dst, const void* src, int src_bytes) {
    asm volatile("cp.async.cg.shared.global [%0], [%1], 16, %2;"
                 :: "r"(dst), "l"(src), "r"(src_bytes) : "memory");
}
__device__ __forceinline__ void cp_commit() {
    asm volatile("cp.async.commit_group;" ::: "memory");
}

__device__ __forceinline__ uint32_t pack2h(__half e0, __half e1) {
    return (uint32_t)__half_as_ushort(e0) |
           ((uint32_t)__half_as_ushort(e1) << 16);
}

__device__ __forceinline__ void split_pack(float v0, float v1,
                                           uint32_t& hi, uint32_t& lo) {
    __half h0 = __float2half_rn(v0);
    __half h1 = __float2half_rn(v1);
    __half l0 = __float2half_rn(v0 - __half2float(h0));
    __half l1 = __float2half_rn(v1 - __half2float(h1));
    hi = pack2h(h0, h1);
    lo = pack2h(l0, l1);
}

// ===========================================================================
// small kernels
// ===========================================================================
__global__ void reset_kernel() {
    if (threadIdx.x < E_NUM) g_cnt[threadIdx.x] = 0;
}

__global__ void gating_kernel(const float* __restrict__ x,
                              const float* __restrict__ wg) {
    int t = blockIdx.x;
    __shared__ float xs[D_DIM];
    __shared__ float vals[E_NUM];
    int tid = threadIdx.x; // 32

    const float4* xr = reinterpret_cast<const float4*>(x + (size_t)t * D_DIM);
    float4* xs4 = reinterpret_cast<float4*>(xs);
    #pragma unroll
    for (int i = tid; i < D_DIM / 4; i += 32) xs4[i] = xr[i];
    __syncwarp();

    if (tid < E_NUM) {
        float acc = 0.f;
        #pragma unroll 8
        for (int d = 0; d < D_DIM; d++) acc += xs[d] * wg[d * E_NUM + tid];
        vals[tid] = acc;
    }
    __syncwarp();

    if (tid == 0) {
        float v1 = -INFINITY, v2 = -INFINITY;
        int i1 = 0, i2 = 0;
        #pragma unroll
        for (int e = 0; e < E_NUM; e++) {
            float v = vals[e];
            if (v > v1) { v2 = v1; i2 = i1; v1 = v; i1 = e; }
            else if (v > v2) { v2 = v; i2 = e; }
        }
        float ex = __expf(v2 - v1);
        float inv = 1.f / (1.f + ex);
        int p1 = atomicAdd(&g_cnt[i1], 1);
        g_tok[i1][p1] = t; g_row[i1][p1] = 2 * t;     g_gate[i1][p1] = inv;
        int p2 = atomicAdd(&g_cnt[i2], 1);
        g_tok[i2][p2] = t; g_row[i2][p2] = 2 * t + 1; g_gate[i2][p2] = ex * inv;
    }
}

// ===========================================================================
// conversion kernels: fp32 -> f16 hi/lo packed pairs
// ===========================================================================
__global__ void convert_x(const float* __restrict__ x) {
    int t = blockIdx.x;
    int c = threadIdx.x;          // 0..255
    float2 v = *reinterpret_cast<const float2*>(x + (size_t)t * D_DIM + 2 * c);
    uint32_t hi, lo;
    split_pack(v.x, v.y, hi, lo);
    g_xs_hi[(size_t)t * (D_DIM / 2) + c] = hi;
    g_xs_lo[(size_t)t * (D_DIM / 2) + c] = lo;
}

// W [E][K][N] fp32 -> Wt [E][K/32][N][16] u32 (packed f16 pairs along k)
template<int K, int N, bool W1>
__global__ __launch_bounds__(256)
void convert_w(const float* __restrict__ w) {
    __shared__ float tile[32][65];
    const int e  = blockIdx.z;
    const int sl = blockIdx.y;
    const int nt = blockIdx.x;    // 64-wide n tile
    const int tid = threadIdx.x;

    const float* src = w + ((size_t)e * K + sl * 32) * N + nt * 64;
    const int kk = tid >> 3;            // 0..31
    const int nn = (tid & 7) * 8;       // 0..56
    float4 v0 = *reinterpret_cast<const float4*>(src + (size_t)kk * N + nn);
    float4 v1 = *reinterpret_cast<const float4*>(src + (size_t)kk * N + nn + 4);
    tile[kk][nn + 0] = v0.x; tile[kk][nn + 1] = v0.y;
    tile[kk][nn + 2] = v0.z; tile[kk][nn + 3] = v0.w;
    tile[kk][nn + 4] = v1.x; tile[kk][nn + 5] = v1.y;
    tile[kk][nn + 6] = v1.z; tile[kk][nn + 7] = v1.w;
    __syncthreads();

    uint32_t* oh = W1 ? g_w1t_hi : g_w2t_hi;
    uint32_t* ol = W1 ? g_w1t_lo : g_w2t_lo;
    const size_t obase = (((size_t)e * (K / 32) + sl) * N + (size_t)nt * 64) * 16;
    const int c = tid & 15;
    #pragma unroll
    for (int b = 0; b < 4; b++) {
        int n = (tid >> 4) + b * 16;   // 0..63
        uint32_t hi, lo;
        split_pack(tile[2 * c][n], tile[2 * c + 1][n], hi, lo);
        oh[obase + (size_t)n * 16 + c] = hi;
        ol[obase + (size_t)n * 16 + c] = lo;
    }
}

// ===========================================================================
// Grouped GEMM via mma.sync f16 (3x split): pre-split operands, cp.async
// double-buffered staging, ldmatrix fragments. CTA tile 128x128, K-slab 32.
// 256 threads, 8 warps of 64x32 tiles. Dynamic smem: 2 x 40960 B.
// ===========================================================================
#define STG_BYTES 40960
#define SUB_BYTES 10240
#define DSM_TOTAL (2 * STG_BYTES)

template<int KDIM, int NTOT, bool RELU, int NSPLIT>
__global__ __launch_bounds__(256)
void moe_mma(const float* __restrict__ bias) {
    const int e     = blockIdx.z / NSPLIT;
    const int split = blockIdx.z % NSPLIT;
    const int cnt = g_cnt[e];
    const int m0  = blockIdx.y * 128;
    if (m0 >= cnt) return;
    const int n0  = blockIdx.x * 128;

    const int KSEG  = KDIM / NSPLIT;
    const int kb    = split * KSEG;
    const int NSLAB = KDIM / 32;
    const int slab0 = kb / 32;
    const int NS    = KSEG / 32;

    extern __shared__ __align__(16) uint32_t dsm[];
    __shared__ float bias_s[128];

    const int tid = threadIdx.x;
    const int wid = tid >> 5, lid = tid & 31;
    const int wm = wid & 1;
    const int wn = wid >> 1;
    const int qid = lid >> 2;
    const int tig = lid & 3;

    const uint32_t smem_base = smem_addr(dsm);

    // device-symbol operand plumbing
    const uint32_t* Ahg = RELU ? g_xs_hi : g_Hs_hi;
    const uint32_t* Alg = RELU ? g_xs_lo : g_Hs_lo;
    const uint32_t* Whg = RELU ? g_w1t_hi : g_w2t_hi;
    const uint32_t* Wlg = RELU ? g_w1t_lo : g_w2t_lo;
    float* DstF = (split == 0) ? g_Y : (split == 1) ? g_Y2
                : (split == 2) ? g_Y3 : g_Y4;

    if (tid < 128) bias_s[tid] = bias[(size_t)e * NTOT + n0 + tid];

    // ---- staging mapping: h = hi/lo select, rr = row within tile ----
    const int h  = tid >> 7;       // 0 = hi, 1 = lo
    const int rr = tid & 127;
    const int mrow = m0 + rr;
    const bool mvalid = (mrow < cnt);
    const int apred = mvalid ? 16 : 0;
    const int aidx = mvalid ? (RELU ? g_tok[e][mrow] : g_row[e][mrow]) : 0;
    const uint32_t* agp = (h ? Alg : Ahg) + (size_t)aidx * (KDIM / 2) + (kb >> 1);
    const uint32_t* wgp = (h ? Wlg : Whg)
        + ((size_t)e * NSLAB + slab0) * NTOT * 16 + (size_t)(n0 + rr) * 16;

    // per-thread staging destinations (byte offsets within a stage)
    const uint32_t dstA = smem_base + (uint32_t)(h * SUB_BYTES + rr * 80);
    const uint32_t dstB = smem_base + (uint32_t)(2 * SUB_BYTES + h * SUB_BYTES + rr * 80);

    // ---- ldmatrix base addresses (byte, stage 0) ----
    const uint32_t aAh = smem_base + (uint32_t)((wm * 64 + (lid & 15)) * 80 + (lid >> 4) * 16);
    const uint32_t aAl = aAh + SUB_BYTES;
    const int brow = wn * 32 + (lid >> 4) * 8 + (lid & 7);
    const int bcol = ((lid >> 3) & 1) * 16;   // bytes
    const uint32_t aBh = smem_base + (uint32_t)(2 * SUB_BYTES + brow * 80 + bcol);
    const uint32_t aBl = aBh + SUB_BYTES;

    float acc[4][4][4];
    #pragma unroll
    for (int i = 0; i < 4; i++)
        #pragma unroll
        for (int j = 0; j < 4; j++)
            #pragma unroll
            for (int q = 0; q < 4; q++) acc[i][j][q] = 0.f;

    // ---- issue copies for slab 0 into stage 0 ----
    #pragma unroll
    for (int j = 0; j < 4; j++) {
        cp_async16(dstA + j * 16, agp + j * 4, apred);
        cp_async16(dstB + j * 16, wgp + j * 4, 16);
    }
    cp_commit();

    for (int s = 0; s < NS; s++) {
        const uint32_t stg = (uint32_t)(s & 1) * STG_BYTES;

        // issue copies for slab s+1 into the other stage
        if (s + 1 < NS) {
            const uint32_t nst = (uint32_t)((s + 1) & 1) * STG_BYTES;
            const uint32_t* ap = agp + (size_t)(s + 1) * 16;
            const uint32_t* bp = wgp + (size_t)(s + 1) * NTOT * 16;
            #pragma unroll
            for (int j = 0; j < 4; j++) {
                cp_async16(dstA + nst + j * 16, ap + j * 4, apred);
                cp_async16(dstB + nst + j * 16, bp + j * 4, 16);
            }
            cp_commit();
            asm volatile("cp.async.wait_group 1;" ::: "memory");
        } else {
            asm volatile("cp.async.wait_group 0;" ::: "memory");
        }
        __syncthreads();   // stage s fully visible to all warps

        #pragma unroll
        for (int ks = 0; ks < 2; ks++) {
            const uint32_t cb = stg + ks * 32;   // stage + 8-u32 column shift
            uint32_t bh[4][2], bl[4][2];
            #pragma unroll
            for (int jj = 0; jj < 2; jj++) {
                ldm_x4(bh[jj * 2][0], bh[jj * 2][1],
                       bh[jj * 2 + 1][0], bh[jj * 2 + 1][1],
                       aBh + jj * (16 * 80) + cb);
                ldm_x4(bl[jj * 2][0], bl[jj * 2][1],
                       bl[jj * 2 + 1][0], bl[jj * 2 + 1][1],
                       aBl + jj * (16 * 80) + cb);
            }
            #pragma unroll
            for (int i = 0; i < 4; i++) {
                uint32_t ah0, ah1, ah2, ah3, al0, al1, al2, al3;
                ldm_x4(ah0, ah1, ah2, ah3, aAh + i * (16 * 80) + cb);
                ldm_x4(al0, al1, al2, al3, aAl + i * (16 * 80) + cb);
                #pragma unroll
                for (int j = 0; j < 4; j++) {
                    mma_f16(acc[i][j], ah0, ah1, ah2, ah3, bh[j][0], bh[j][1]);
                    mma_f16(acc[i][j], al0, al1, al2, al3, bh[j][0], bh[j][1]);
                    mma_f16(acc[i][j], ah0, ah1, ah2, ah3, bl[j][0], bl[j][1]);
                }
            }
        }
        __syncthreads();   // all warps done with stage s before it is refilled
    }

    // ---- epilogue ----
    const bool add_bias = RELU || (split == 0);
    #pragma unroll
    for (int i = 0; i < 4; i++) {
        const int mr0 = m0 + wm * 64 + i * 16 + qid;
        const int mr1 = mr0 + 8;
        const bool v0 = (mr0 < cnt), v1 = (mr1 < cnt);
        const int dr0 = v0 ? g_row[e][mr0] : 0;
        const int dr1 = v1 ? g_row[e][mr1] : 0;
        const float gt0 = RELU ? 1.f : (v0 ? g_gate[e][mr0] : 0.f);
        const float gt1 = RELU ? 1.f : (v1 ? g_gate[e][mr1] : 0.f);
        #pragma unroll
        for (int j = 0; j < 4; j++) {
            const int cl = wn * 32 + j * 8 + tig * 2;
            const float bz0 = add_bias ? bias_s[cl]     : 0.f;
            const float bz1 = add_bias ? bias_s[cl + 1] : 0.f;
            if (RELU) {
                const size_t hcol = (size_t)((n0 + cl) >> 1);
                if (v0) {
                    float y0 = fmaxf(acc[i][j][0] + bz0, 0.f);
                    float y1 = fmaxf(acc[i][j][1] + bz1, 0.f);
                    uint32_t hi, lo;
                    split_pack(y0, y1, hi, lo);
                    g_Hs_hi[(size_t)dr0 * (NTOT / 2) + hcol] = hi;
                    g_Hs_lo[(size_t)dr0 * (NTOT / 2) + hcol] = lo;
                }
                if (v1) {
                    float y0 = fmaxf(acc[i][j][2] + bz0, 0.f);
                    float y1 = fmaxf(acc[i][j][3] + bz1, 0.f);
                    uint32_t hi, lo;
                    split_pack(y0, y1, hi, lo);
                    g_Hs_hi[(size_t)dr1 * (NTOT / 2) + hcol] = hi;
                    g_Hs_lo[(size_t)dr1 * (NTOT / 2) + hcol] = lo;
                }
            } else {
                if (v0) {
                    float2 o;
                    o.x = gt0 * (acc[i][j][0] + bz0);
                    o.y = gt0 * (acc[i][j][1] + bz1);
                    *reinterpret_cast<float2*>(DstF + (size_t)dr0 * NTOT + n0 + cl) = o;
                }
                if (v1) {
                    float2 o;
                    o.x = gt1 * (acc[i][j][2] + bz0);
                    o.y = gt1 * (acc[i][j][3] + bz1);
                    *reinterpret_cast<float2*>(DstF + (size_t)dr1 * NTOT + n0 + cl) = o;
                }
            }
        }
    }
}

// ===========================================================================
// out[t][d] = sum over 4 split buffers x 2 slot rows
__global__ void combine_kernel(float* __restrict__ out) {
    int i = blockIdx.x * blockDim.x + threadIdx.x;
    if (i >= N_TOK * D_DIM / 4) return;
    int t  = i / (D_DIM / 4);
    int d4 = i % (D_DIM / 4);
    const size_t r0 = (size_t)(2 * t) * D_DIM;
    const size_t r1 = (size_t)(2 * t + 1) * D_DIM;
    float4 acc = make_float4(0.f, 0.f, 0.f, 0.f);
    const float* bufs[4] = {g_Y, g_Y2, g_Y3, g_Y4};
    #pragma unroll
    for (int b = 0; b < 4; b++) {
        float4 p = *(reinterpret_cast<const float4*>(bufs[b] + r0) + d4);
        float4 q = *(reinterpret_cast<const float4*>(bufs[b] + r1) + d4);
        acc.x += p.x + q.x; acc.y += p.y + q.y;
        acc.z += p.z + q.z; acc.w += p.w + q.w;
    }
    reinterpret_cast<float4*>(out)[i] = acc;
}

__global__ void aux_kernel(float* __restrict__ out, int out_size) {
    __shared__ float imp[E_NUM];
    int w = threadIdx.x >> 5, lane = threadIdx.x & 31;
    int cnt = g_cnt[w];
    float s = 0.f;
    for (int i = lane; i < cnt; i += 32) s += g_gate[w][i];
    #pragma unroll
    for (int off = 16; off > 0; off >>= 1) s += __shfl_down_sync(0xffffffffu, s, off);
    if (lane == 0) imp[w] = s;
    __syncthreads();
    if (threadIdx.x == 0) {
        float mean = 0.f;
        #pragma unroll
        for (int e = 0; e < E_NUM; e++) mean += imp[e];
        mean *= (1.f / E_NUM);
        float var = 0.f;
        #pragma unroll
        for (int e = 0; e < E_NUM; e++) { float d = imp[e] - mean; var += d * d; }
        var *= (1.f / (E_NUM - 1));
        float aux = 0.01f * var / (mean * mean + 1e-10f);
        if (out_size > N_TOK * D_DIM) out[out_size - 1] = aux;
    }
}

// ===========================================================================
extern "C" void kernel_launch(void* const* d_in, const int* in_sizes, int n_in,
                              void* d_out, int out_size) {
    const float* x  = (const float*)d_in[0];
    const float* wg = (const float*)d_in[1];
    const float* w1 = (const float*)d_in[2];
    const float* b1 = (const float*)d_in[3];
    const float* w2 = (const float*)d_in[4];
    const float* b2 = (const float*)d_in[5];
    float* out = (float*)d_out;

    cudaFuncSetAttribute(moe_mma<D_DIM, H_DIM, true, 1>,
                         cudaFuncAttributeMaxDynamicSharedMemorySize, DSM_TOTAL);
    cudaFuncSetAttribute(moe_mma<H_DIM, D_DIM, false, 4>,
                         cudaFuncAttributeMaxDynamicSharedMemorySize, DSM_TOTAL);

    reset_kernel<<<1, 32>>>();
    gating_kernel<<<N_TOK, 32>>>(x, wg);
    // pre-split operands to f16 hi/lo
    convert_x<<<N_TOK, 256>>>(x);
    convert_w<D_DIM, H_DIM, true ><<<dim3(H_DIM / 64, D_DIM / 32, E_NUM), 256>>>(w1);
    convert_w<H_DIM, D_DIM, false><<<dim3(D_DIM / 64, H_DIM / 32, E_NUM), 256>>>(w2);
    // GEMM1: g_Hs = relu(Xg @ W1 + b1); grid (16, 16, 16)
    moe_mma<D_DIM, H_DIM, true, 1>
        <<<dim3(H_DIM / 128, N_TOK / 128, E_NUM), 256, DSM_TOTAL>>>(b1);
    // GEMM2 split-K=4: g_Y..g_Y4 = gate*(Hg @ W2 [+ b2 on split0]); grid (4, 16, 64)
    moe_mma<H_DIM, D_DIM, false, 4>
        <<<dim3(D_DIM / 128, N_TOK / 128, E_NUM * 4), 256, DSM_TOTAL>>>(b2);
    combine_kernel<<<(N_TOK * D_DIM / 4 + 255) / 256, 256>>>(out);
    aux_kernel<<<1, 512>>>(out, out_size);
}

// round 16
// speedup vs baseline: 1.2805x; 1.1550x over previous
#include <cuda_runtime.h>
#include <cuda_fp16.h>
#include <cstdint>
#include <math.h>

// Problem constants
#define P_NUM 64
#define B_NUM 32
#define D_DIM 512
#define H_DIM 2048
#define E_NUM 16
#define N_TOK (P_NUM * B_NUM)        // 2048 tokens
#define N_ROWS (N_TOK * 2)           // 4096 assignment rows

// ---- device scratch. NEVER passed as kernel args from host (host-shadow/ATS
// trap confirmed R10). All kernels reference these symbols in device code. ----
__device__ int   g_cnt[E_NUM];
__device__ int   g_tok [E_NUM][N_TOK];
__device__ int   g_row [E_NUM][N_TOK];
__device__ float g_gate[E_NUM][N_TOK];

// pre-split f16 operands (u32 = packed pair of f16 along k)
__device__ __align__(16) uint32_t g_xs_hi[(size_t)N_TOK * (D_DIM / 2)];
__device__ __align__(16) uint32_t g_xs_lo[(size_t)N_TOK * (D_DIM / 2)];
__device__ __align__(16) uint32_t g_Hs_hi[(size_t)N_ROWS * (H_DIM / 2)];
__device__ __align__(16) uint32_t g_Hs_lo[(size_t)N_ROWS * (H_DIM / 2)];
// W transposed, slab-major: [E][K/32][N][16] u32
__device__ __align__(16) uint32_t g_w1t_hi[(size_t)E_NUM * (D_DIM / 32) * H_DIM * 16];
__device__ __align__(16) uint32_t g_w1t_lo[(size_t)E_NUM * (D_DIM / 32) * H_DIM * 16];
__device__ __align__(16) uint32_t g_w2t_hi[(size_t)E_NUM * (H_DIM / 32) * D_DIM * 16];
__device__ __align__(16) uint32_t g_w2t_lo[(size_t)E_NUM * (H_DIM / 32) * D_DIM * 16];

__device__ float g_Y [(size_t)N_ROWS * D_DIM]; // split-0 output
__device__ float g_Y2[(size_t)N_ROWS * D_DIM]; // split-1 output

// ===========================================================================
// helpers
// ===========================================================================
__device__ __forceinline__ void mma_f16(float* c,
                                        uint32_t a0, uint32_t a1, uint32_t a2, uint32_t a3,
                                        uint32_t b0, uint32_t b1) {
    asm volatile(
        "mma.sync.aligned.m16n8k16.row.col.f32.f16.f16.f32 "
        "{%0,%1,%2,%3}, {%4,%5,%6,%7}, {%8,%9}, {%0,%1,%2,%3};"
        : "+f"(c[0]), "+f"(c[1]), "+f"(c[2]), "+f"(c[3])
        : "r"(a0), "r"(a1), "r"(a2), "r"(a3), "r"(b0), "r"(b1));
}

__device__ __forceinline__ void ldm_x4(uint32_t& r0, uint32_t& r1,
                                       uint32_t& r2, uint32_t& r3, uint32_t addr) {
    asm volatile(
        "ldmatrix.sync.aligned.m8n8.x4.shared.b16 {%0,%1,%2,%3}, [%4];"
        : "=r"(r0), "=r"(r1), "=r"(r2), "=r"(r3) : "r"(addr));
}

__device__ __forceinline__ uint32_t smem_addr(const void* p) {
    return (uint32_t)__cvta_generic_to_shared(p);
}

__device__ __forceinline__ uint32_t pack2h(__half e0, __half e1) {
    return (uint32_t)__half_as_ushort(e0) |
           ((uint32_t)__half_as_ushort(e1) << 16);
}

__device__ __forceinline__ void split_pack(float v0, float v1,
                                           uint32_t& hi, uint32_t& lo) {
    __half h0 = __float2half_rn(v0);
    __half h1 = __float2half_rn(v1);
    __half l0 = __float2half_rn(v0 - __half2float(h0));
    __half l1 = __float2half_rn(v1 - __half2float(h1));
    hi = pack2h(h0, h1);
    lo = pack2h(l0, l1);
}

// ===========================================================================
// small kernels
// ===========================================================================
__global__ void reset_kernel() {
    if (threadIdx.x < E_NUM) g_cnt[threadIdx.x] = 0;
}

// Fused: gate computation + x -> f16 hi/lo split (one x read)
__global__ __launch_bounds__(256)
void gating_kernel(const float* __restrict__ x,
                   const float* __restrict__ wg) {
    int t = blockIdx.x;
    __shared__ float xs[D_DIM];
    __shared__ float vals[E_NUM];
    int tid = threadIdx.x; // 256

    // each thread: one float2 of this token's row -> smem + split store
    float2 v = *reinterpret_cast<const float2*>(x + (size_t)t * D_DIM + 2 * tid);
    xs[2 * tid]     = v.x;
    xs[2 * tid + 1] = v.y;
    uint32_t hi, lo;
    split_pack(v.x, v.y, hi, lo);
    g_xs_hi[(size_t)t * (D_DIM / 2) + tid] = hi;
    g_xs_lo[(size_t)t * (D_DIM / 2) + tid] = lo;
    __syncthreads();

    if (tid < E_NUM) {
        float acc = 0.f;
        #pragma unroll 8
        for (int d = 0; d < D_DIM; d++) acc += xs[d] * wg[d * E_NUM + tid];
        vals[tid] = acc;
    }
    __syncthreads();

    if (tid == 0) {
        float v1 = -INFINITY, v2 = -INFINITY;
        int i1 = 0, i2 = 0;
        #pragma unroll
        for (int e = 0; e < E_NUM; e++) {
            float w = vals[e];
            if (w > v1) { v2 = v1; i2 = i1; v1 = w; i1 = e; }
            else if (w > v2) { v2 = w; i2 = e; }
        }
        float ex = __expf(v2 - v1);
        float inv = 1.f / (1.f + ex);
        int p1 = atomicAdd(&g_cnt[i1], 1);
        g_tok[i1][p1] = t; g_row[i1][p1] = 2 * t;     g_gate[i1][p1] = inv;
        int p2 = atomicAdd(&g_cnt[i2], 1);
        g_tok[i2][p2] = t; g_row[i2][p2] = 2 * t + 1; g_gate[i2][p2] = ex * inv;
    }
}

// W [E][K][N] fp32 -> Wt [E][K/32][N][16] u32 (packed f16 pairs along k)
template<int K, int N, bool W1>
__global__ __launch_bounds__(256)
void convert_w(const float* __restrict__ w) {
    __shared__ float tile[32][65];
    const int e  = blockIdx.z;
    const int sl = blockIdx.y;
    const int nt = blockIdx.x;    // 64-wide n tile
    const int tid = threadIdx.x;

    const float* src = w + ((size_t)e * K + sl * 32) * N + nt * 64;
    const int kk = tid >> 3;            // 0..31
    const int nn = (tid & 7) * 8;       // 0..56
    float4 v0 = *reinterpret_cast<const float4*>(src + (size_t)kk * N + nn);
    float4 v1 = *reinterpret_cast<const float4*>(src + (size_t)kk * N + nn + 4);
    tile[kk][nn + 0] = v0.x; tile[kk][nn + 1] = v0.y;
    tile[kk][nn + 2] = v0.z; tile[kk][nn + 3] = v0.w;
    tile[kk][nn + 4] = v1.x; tile[kk][nn + 5] = v1.y;
    tile[kk][nn + 6] = v1.z; tile[kk][nn + 7] = v1.w;
    __syncthreads();

    uint32_t* oh = W1 ? g_w1t_hi : g_w2t_hi;
    uint32_t* ol = W1 ? g_w1t_lo : g_w2t_lo;
    const size_t obase = (((size_t)e * (K / 32) + sl) * N + (size_t)nt * 64) * 16;
    const int c = tid & 15;
    #pragma unroll
    for (int b = 0; b < 4; b++) {
        int n = (tid >> 4) + b * 16;   // 0..63
        uint32_t hi, lo;
        split_pack(tile[2 * c][n], tile[2 * c + 1][n], hi, lo);
        oh[obase + (size_t)n * 16 + c] = hi;
        ol[obase + (size_t)n * 16 + c] = lo;
    }
}

// ===========================================================================
// Grouped GEMM via mma.sync f16 (3x split): pre-split operands, LDG register
// prefetch, DOUBLE-BUFFERED smem with ONE barrier per K-slab, ldmatrix
// fragments. CTA tile 128x128, K-slab 32, 8 warps of 64x32 tiles.
// Stage (bytes): [Ah 128*80 | Al 128*80 | Bh 128*80 | Bl 128*80] = 40960.
// ===========================================================================
#define STG_BYTES 40960
#define STG_WORDS 10240
#define SUB_BYTES 10240
#define SUB_WORDS 2560
#define DSM_TOTAL (2 * STG_BYTES)

template<int KDIM, int NTOT, bool RELU, int NSPLIT>
__global__ __launch_bounds__(256)
void moe_mma(const float* __restrict__ bias) {
    const int e     = blockIdx.z / NSPLIT;
    const int split = blockIdx.z % NSPLIT;
    const int cnt = g_cnt[e];
    const int m0  = blockIdx.y * 128;
    if (m0 >= cnt) return;
    const int n0  = blockIdx.x * 128;

    const int KSEG  = KDIM / NSPLIT;
    const int kb    = split * KSEG;
    const int NSLAB = KDIM / 32;
    const int slab0 = kb / 32;
    const int NS    = KSEG / 32;

    extern __shared__ __align__(16) uint32_t dsm[];
    __shared__ float bias_s[128];

    const int tid = threadIdx.x;
    const int wid = tid >> 5, lid = tid & 31;
    const int wm = wid & 1;
    const int wn = wid >> 1;
    const int qid = lid >> 2;
    const int tig = lid & 3;

    const uint32_t smem_base = smem_addr(dsm);

    // device-symbol operand plumbing
    const uint32_t* Ahg = RELU ? g_xs_hi : g_Hs_hi;
    const uint32_t* Alg = RELU ? g_xs_lo : g_Hs_lo;
    const uint32_t* Whg = RELU ? g_w1t_hi : g_w2t_hi;
    const uint32_t* Wlg = RELU ? g_w1t_lo : g_w2t_lo;
    float* DstF = (split == 0) ? g_Y : g_Y2;

    if (tid < 128) bias_s[tid] = bias[(size_t)e * NTOT + n0 + tid];

    // ---- staging mapping: h = hi/lo select, rr = row within tile ----
    const int h  = tid >> 7;       // 0 = hi, 1 = lo
    const int rr = tid & 127;
    const int mrow = m0 + rr;
    const bool mvalid = (mrow < cnt);
    const int aidx = mvalid ? (RELU ? g_tok[e][mrow] : g_row[e][mrow]) : 0;
    const uint32_t* agp = (h ? Alg : Ahg) + (size_t)aidx * (KDIM / 2) + (kb >> 1);
    const uint32_t* wgp = (h ? Wlg : Whg)
        + ((size_t)e * NSLAB + slab0) * NTOT * 16 + (size_t)(n0 + rr) * 16;

    // per-thread staging destinations (word offsets within a stage)
    const uint32_t dA = (uint32_t)(h * SUB_WORDS + rr * 20);
    const uint32_t dB = (uint32_t)(2 * SUB_WORDS + h * SUB_WORDS + rr * 20);

    // ---- ldmatrix base addresses (byte, stage 0) ----
    const uint32_t aAh = smem_base + (uint32_t)((wm * 64 + (lid & 15)) * 80 + (lid >> 4) * 16);
    const uint32_t aAl = aAh + SUB_BYTES;
    const int brow = wn * 32 + (lid >> 4) * 8 + (lid & 7);
    const int bcol = ((lid >> 3) & 1) * 16;   // bytes
    const uint32_t aBh = smem_base + (uint32_t)(2 * SUB_BYTES + brow * 80 + bcol);
    const uint32_t aBl = aBh + SUB_BYTES;

    float acc[4][4][4];
    #pragma unroll
    for (int i = 0; i < 4; i++)
        #pragma unroll
        for (int j = 0; j < 4; j++)
            #pragma unroll
            for (int q = 0; q < 4; q++) acc[i][j][q] = 0.f;

    uint4 pA[4], pB[4];
    const uint4 z4 = make_uint4(0u, 0u, 0u, 0u);
    #pragma unroll
    for (int j = 0; j < 4; j++) {
        pA[j] = mvalid ? *reinterpret_cast<const uint4*>(agp + j * 4) : z4;
        pB[j] = *reinterpret_cast<const uint4*>(wgp + j * 4);
    }

    for (int s = 0; s < NS; s++) {
        const uint32_t stw = (uint32_t)(s & 1) * STG_WORDS;  // stage word offset
        const uint32_t stb = (uint32_t)(s & 1) * STG_BYTES;  // stage byte offset

        // ---- store prefetched slab s into stage s&1 ----
        #pragma unroll
        for (int j = 0; j < 4; j++) {
            *reinterpret_cast<uint4*>(dsm + stw + dA + j * 4) = pA[j];
            *reinterpret_cast<uint4*>(dsm + stw + dB + j * 4) = pB[j];
        }

        // ---- prefetch slab s+1 into registers (overlaps barrier+compute) ----
        if (s + 1 < NS) {
            const uint32_t* ap = agp + (size_t)(s + 1) * 16;
            const uint32_t* bp = wgp + (size_t)(s + 1) * NTOT * 16;
            #pragma unroll
            for (int j = 0; j < 4; j++) {
                pA[j] = mvalid ? *reinterpret_cast<const uint4*>(ap + j * 4) : z4;
                pB[j] = *reinterpret_cast<const uint4*>(bp + j * 4);
            }
        }

        __syncthreads();   // single barrier: stage s&1 stores visible; also
                           // separates this stage's reads from its re-write
                           // two slabs later (see ordering argument).

        // ---- compute slab s from stage s&1 ----
        #pragma unroll
        for (int ks = 0; ks < 2; ks++) {
            const uint32_t cb = stb + ks * 32;
            uint32_t bh[4][2], bl[4][2];
            #pragma unroll
            for (int jj = 0; jj < 2; jj++) {
                ldm_x4(bh[jj * 2][0], bh[jj * 2][1],
                       bh[jj * 2 + 1][0], bh[jj * 2 + 1][1],
                       aBh + jj * (16 * 80) + cb);
                ldm_x4(bl[jj * 2][0], bl[jj * 2][1],
                       bl[jj * 2 + 1][0], bl[jj * 2 + 1][1],
                       aBl + jj * (16 * 80) + cb);
            }
            #pragma unroll
            for (int i = 0; i < 4; i++) {
                uint32_t ah0, ah1, ah2, ah3, al0, al1, al2, al3;
                ldm_x4(ah0, ah1, ah2, ah3, aAh + i * (16 * 80) + cb);
                ldm_x4(al0, al1, al2, al3, aAl + i * (16 * 80) + cb);
                #pragma unroll
                for (int j = 0; j < 4; j++) {
                    mma_f16(acc[i][j], ah0, ah1, ah2, ah3, bh[j][0], bh[j][1]);
                    mma_f16(acc[i][j], al0, al1, al2, al3, bh[j][0], bh[j][1]);
                    mma_f16(acc[i][j], ah0, ah1, ah2, ah3, bl[j][0], bl[j][1]);
                }
            }
        }
    }

    // ---- epilogue ----
    const bool add_bias = RELU || (split == 0);
    #pragma unroll
    for (int i = 0; i < 4; i++) {
        const int mr0 = m0 + wm * 64 + i * 16 + qid;
        const int mr1 = mr0 + 8;
        const bool v0 = (mr0 < cnt), v1 = (mr1 < cnt);
        const int dr0 = v0 ? g_row[e][mr0] : 0;
        const int dr1 = v1 ? g_row[e][mr1] : 0;
        const float gt0 = RELU ? 1.f : (v0 ? g_gate[e][mr0] : 0.f);
        const float gt1 = RELU ? 1.f : (v1 ? g_gate[e][mr1] : 0.f);
        #pragma unroll
        for (int j = 0; j < 4; j++) {
            const int cl = wn * 32 + j * 8 + tig * 2;
            const float bz0 = add_bias ? bias_s[cl]     : 0.f;
            const float bz1 = add_bias ? bias_s[cl + 1] : 0.f;
            if (RELU) {
                const size_t hcol = (size_t)((n0 + cl) >> 1);
                if (v0) {
                    float y0 = fmaxf(acc[i][j][0] + bz0, 0.f);
                    float y1 = fmaxf(acc[i][j][1] + bz1, 0.f);
                    uint32_t hi, lo;
                    split_pack(y0, y1, hi, lo);
                    g_Hs_hi[(size_t)dr0 * (NTOT / 2) + hcol] = hi;
                    g_Hs_lo[(size_t)dr0 * (NTOT / 2) + hcol] = lo;
                }
                if (v1) {
                    float y0 = fmaxf(acc[i][j][2] + bz0, 0.f);
                    float y1 = fmaxf(acc[i][j][3] + bz1, 0.f);
                    uint32_t hi, lo;
                    split_pack(y0, y1, hi, lo);
                    g_Hs_hi[(size_t)dr1 * (NTOT / 2) + hcol] = hi;
                    g_Hs_lo[(size_t)dr1 * (NTOT / 2) + hcol] = lo;
                }
            } else {
                if (v0) {
                    float2 o;
                    o.x = gt0 * (acc[i][j][0] + bz0);
                    o.y = gt0 * (acc[i][j][1] + bz1);
                    *reinterpret_cast<float2*>(DstF + (size_t)dr0 * NTOT + n0 + cl) = o;
                }
                if (v1) {
                    float2 o;
                    o.x = gt1 * (acc[i][j][2] + bz0);
                    o.y = gt1 * (acc[i][j][3] + bz1);
                    *reinterpret_cast<float2*>(DstF + (size_t)dr1 * NTOT + n0 + cl) = o;
                }
            }
        }
    }
}

// ===========================================================================
// out[t][d] = Y0[2t]+Y0[2t+1]+Y1[2t]+Y1[2t+1]
__global__ void combine_kernel(float* __restrict__ out) {
    int i = blockIdx.x * blockDim.x + threadIdx.x;
    if (i >= N_TOK * D_DIM / 4) return;
    int t  = i / (D_DIM / 4);
    int d4 = i % (D_DIM / 4);
    const float4* a0 = reinterpret_cast<const float4*>(g_Y  + (size_t)(2 * t)     * D_DIM) + d4;
    const float4* a1 = reinterpret_cast<const float4*>(g_Y  + (size_t)(2 * t + 1) * D_DIM) + d4;
    const float4* b0 = reinterpret_cast<const float4*>(g_Y2 + (size_t)(2 * t)     * D_DIM) + d4;
    const float4* b1 = reinterpret_cast<const float4*>(g_Y2 + (size_t)(2 * t + 1) * D_DIM) + d4;
    float4 p = *a0, q = *a1, r = *b0, s = *b1;
    reinterpret_cast<float4*>(out)[i] =
        make_float4(p.x + q.x + r.x + s.x, p.y + q.y + r.y + s.y,
                    p.z + q.z + r.z + s.z, p.w + q.w + r.w + s.w);
}

__global__ void aux_kernel(float* __restrict__ out, int out_size) {
    __shared__ float imp[E_NUM];
    int w = threadIdx.x >> 5, lane = threadIdx.x & 31;
    int cnt = g_cnt[w];
    float s = 0.f;
    for (int i = lane; i < cnt; i += 32) s += g_gate[w][i];
    #pragma unroll
    for (int off = 16; off > 0; off >>= 1) s += __shfl_down_sync(0xffffffffu, s, off);
    if (lane == 0) imp[w] = s;
    __syncthreads();
    if (threadIdx.x == 0) {
        float mean = 0.f;
        #pragma unroll
        for (int e = 0; e < E_NUM; e++) mean += imp[e];
        mean *= (1.f / E_NUM);
        float var = 0.f;
        #pragma unroll
        for (int e = 0; e < E_NUM; e++) { float d = imp[e] - mean; var += d * d; }
        var *= (1.f / (E_NUM - 1));
        float aux = 0.01f * var / (mean * mean + 1e-10f);
        if (out_size > N_TOK * D_DIM) out[out_size - 1] = aux;
    }
}

// ===========================================================================
extern "C" void kernel_launch(void* const* d_in, const int* in_sizes, int n_in,
                              void* d_out, int out_size) {
    const float* x  = (const float*)d_in[0];
    const float* wg = (const float*)d_in[1];
    const float* w1 = (const float*)d_in[2];
    const float* b1 = (const float*)d_in[3];
    const float* w2 = (const float*)d_in[4];
    const float* b2 = (const float*)d_in[5];
    float* out = (float*)d_out;

    cudaFuncSetAttribute(moe_mma<D_DIM, H_DIM, true, 1>,
                         cudaFuncAttributeMaxDynamicSharedMemorySize, DSM_TOTAL);
    cudaFuncSetAttribute(moe_mma<H_DIM, D_DIM, false, 2>,
                         cudaFuncAttributeMaxDynamicSharedMemorySize, DSM_TOTAL);

    reset_kernel<<<1, 32>>>();
    gating_kernel<<<N_TOK, 256>>>(x, wg);      // fused gate + x split
    convert_w<D_DIM, H_DIM, true ><<<dim3(H_DIM / 64, D_DIM / 32, E_NUM), 256>>>(w1);
    convert_w<H_DIM, D_DIM, false><<<dim3(D_DIM / 64, H_DIM / 32, E_NUM), 256>>>(w2);
    // GEMM1: g_Hs = relu(Xg @ W1 + b1); grid (16, 16, 16)
    moe_mma<D_DIM, H_DIM, true, 1>
        <<<dim3(H_DIM / 128, N_TOK / 128, E_NUM), 256, DSM_TOTAL>>>(b1);
    // GEMM2 split-K=2: g_Y/g_Y2 = gate*(Hg @ W2 [+ b2 on split0]); grid (4, 16, 32)
    moe_mma<H_DIM, D_DIM, false, 2>
        <<<dim3(D_DIM / 128, N_TOK / 128, E_NUM * 2), 256, DSM_TOTAL>>>(b2);
    combine_kernel<<<(N_TOK * D_DIM / 4 + 255) / 256, 256>>>(out);
    aux_kernel<<<1, 512>>>(out, out_size);
}